// round 10
// baseline (speedup 1.0000x reference)
#include <cuda_runtime.h>
#include <cuda_bf16.h>

#define N_NODES    50000
#define N_EDGES    800000
#define CH         128
#define OUT_CH     10
#define NUM_GRAPHS 128

// -------- persistent scratch (device globals; referenced ONLY inside kernels,
//          NEVER passed as host-side launch arguments) --------
__device__ int g_e64_flag;
__device__ int g_b64_flag;
__device__ __align__(16) int   g_eidx[2 * N_EDGES];
__device__ __align__(16) int   g_batch[N_NODES];
__device__ __align__(16) int   g_deg_i[N_NODES];
__device__ __align__(16) float g_dinv[N_NODES];
__device__ __align__(16) float g_h[(size_t)N_NODES * CH];
__device__ __align__(16) float g_agg[(size_t)N_NODES * CH];
__device__ __align__(16) float g_pool[NUM_GRAPHS * CH];
__device__ __align__(16) float g_cnt[NUM_GRAPHS];

// ---------------------------------------------------------------------------
// dtype probes (edge: head odd-words; batch: tail odd-words of first N words)
__global__ __launch_bounds__(512) void detect_kernel(
    const unsigned int* __restrict__ ebuf, const unsigned int* __restrict__ bbuf)
{
    int t = threadIdx.x;
    int bad_e = (ebuf[2 * t + 1] != 0u);
    int widx = (N_NODES - 1024) + 2 * t + 1;
    int bad_b = (bbuf[widx] != 0u);
    int any_e = __syncthreads_or(bad_e);
    int any_b = __syncthreads_or(bad_b);
    if (t == 0) { g_e64_flag = any_e ? 0 : 1; g_b64_flag = any_b ? 0 : 1; }
}

__global__ void conv_edges_kernel(const unsigned int* __restrict__ ebuf) {
    int i = blockIdx.x * blockDim.x + threadIdx.x;
    if (i >= 2 * N_EDGES) return;
    g_eidx[i] = g_e64_flag ? (int)ebuf[2 * i] : (int)ebuf[i];
}

__global__ void conv_batch_kernel(const unsigned int* __restrict__ bbuf) {
    int i = blockIdx.x * blockDim.x + threadIdx.x;
    if (i >= N_NODES) return;
    int v = g_b64_flag ? (int)bbuf[2 * i] : (int)bbuf[i];
    if ((unsigned)v >= NUM_GRAPHS) v = 0;
    g_batch[i] = v;
}

// ---------------------------------------------------------------------------
__global__ void zero_kernel() {
    int i = blockIdx.x * blockDim.x + threadIdx.x;
    if (i < N_NODES)         g_deg_i[i] = 0;
    if (i < NUM_GRAPHS * CH) g_pool[i] = 0.f;
    if (i < NUM_GRAPHS)      g_cnt[i] = 0.f;
}

__global__ void deg_kernel() {
    int e = blockIdx.x * blockDim.x + threadIdx.x;
    if (e >= N_EDGES) return;
    unsigned d = (unsigned)g_eidx[N_EDGES + e];
    if (d < N_NODES) atomicAdd(&g_deg_i[d], 1);
}

__global__ void dinv_kernel() {
    int i = blockIdx.x * blockDim.x + threadIdx.x;
    if (i < N_NODES) g_dinv[i] = rsqrtf((float)g_deg_i[i] + 1.0f);
}

// ---------------------------------------------------------------------------
// layer-1 GEMM: g_h = x @ W1.  W1[k*CH + t] as in the reference (x @ W).
// 16 rows/block, 128 threads, thread t = output column.
__global__ __launch_bounds__(128) void gemm_l1_kernel(
    const float* __restrict__ X, const float* __restrict__ W)
{
    __shared__ float xs[16][CH];
    const int t = threadIdx.x;
    const int row0 = blockIdx.x * 16;
#pragma unroll
    for (int r = 0; r < 16; r++) {
        int row = row0 + r;
        xs[r][t] = (row < N_NODES) ? X[(size_t)row * CH + t] : 0.f;
    }
    __syncthreads();
    float acc[16];
#pragma unroll
    for (int r = 0; r < 16; r++) acc[r] = 0.f;
#pragma unroll 4
    for (int k = 0; k < CH; k++) {
        float w = W[k * CH + t];
#pragma unroll
        for (int r = 0; r < 16; r++)
            acc[r] = fmaf(xs[r][k], w, acc[r]);
    }
#pragma unroll
    for (int r = 0; r < 16; r++) {
        int row = row0 + r;
        if (row < N_NODES) g_h[(size_t)row * CH + t] = acc[r];
    }
}

// layer-2 GEMM: g_h = relu(g_agg + b1) @ W2   (activation fused on load)
__global__ __launch_bounds__(128) void gemm_l2_kernel(
    const float* __restrict__ W, const float* __restrict__ b1)
{
    __shared__ float xs[16][CH];
    const int t = threadIdx.x;
    const int row0 = blockIdx.x * 16;
    float bias = b1[t];
#pragma unroll
    for (int r = 0; r < 16; r++) {
        int row = row0 + r;
        float v = (row < N_NODES) ? g_agg[(size_t)row * CH + t] : 0.f;
        xs[r][t] = fmaxf(v + bias, 0.f);
    }
    __syncthreads();
    float acc[16];
#pragma unroll
    for (int r = 0; r < 16; r++) acc[r] = 0.f;
#pragma unroll 4
    for (int k = 0; k < CH; k++) {
        float w = W[k * CH + t];
#pragma unroll
        for (int r = 0; r < 16; r++)
            acc[r] = fmaf(xs[r][k], w, acc[r]);
    }
#pragma unroll
    for (int r = 0; r < 16; r++) {
        int row = row0 + r;
        if (row < N_NODES) g_h[(size_t)row * CH + t] = acc[r];
    }
}

// ---------------------------------------------------------------------------
// agg[n][c] = dinv[n]^2 * h[n][c]   (self-loop term; initializes every element)
__global__ void selfloop_init_kernel() {
    int i = blockIdx.x * blockDim.x + threadIdx.x;
    if (i >= N_NODES * CH) return;
    int node = i >> 7;
    float dv = g_dinv[node];
    g_agg[i] = dv * dv * g_h[i];
}

// one warp per edge: agg[dst][c] += dinv[src]*dinv[dst] * h[src][c]
__global__ __launch_bounds__(256) void scatter_kernel() {
    int e = (blockIdx.x * blockDim.x + threadIdx.x) >> 5;
    if (e >= N_EDGES) return;
    int lane = threadIdx.x & 31;
    unsigned s = (unsigned)g_eidx[e];
    unsigned d = (unsigned)g_eidx[N_EDGES + e];
    if (s >= N_NODES || d >= N_NODES) return;
    float nv = g_dinv[s] * g_dinv[d];
    const float* hs = g_h   + (size_t)s * CH;
    float*       ad = g_agg + (size_t)d * CH;
#pragma unroll
    for (int k = 0; k < 4; k++) {
        int c = lane + 32 * k;
        atomicAdd(ad + c, nv * hs[c]);
    }
}

// ---------------------------------------------------------------------------
// pool[batch[n]][c] += relu(agg[n][c] + b2[c])
__global__ void pool_kernel(const float* __restrict__ b2) {
    int i = blockIdx.x * blockDim.x + threadIdx.x;
    if (i >= N_NODES * CH) return;
    int node = i >> 7;
    int c = i & (CH - 1);
    int g = g_batch[node];
    float v = fmaxf(g_agg[i] + b2[c], 0.f);
    atomicAdd(&g_pool[g * CH + c], v);
}

__global__ void cnt_kernel() {
    int i = blockIdx.x * blockDim.x + threadIdx.x;
    if (i >= N_NODES) return;
    atomicAdd(&g_cnt[g_batch[i]], 1.0f);
}

// out[g] = (pool[g]/max(cnt,1)) @ Wc + bc
__global__ __launch_bounds__(CH) void cls_kernel(
    const float* __restrict__ Wc, const float* __restrict__ bc,
    float* __restrict__ out)
{
    __shared__ float s[CH];
    int g = blockIdx.x;
    int t = threadIdx.x;
    float inv = 1.0f / fmaxf(g_cnt[g], 1.0f);
    s[t] = g_pool[g * CH + t] * inv;
    __syncthreads();
    if (t < OUT_CH) {
        float o = bc[t];
#pragma unroll 8
        for (int k = 0; k < CH; k++)
            o = fmaf(s[k], Wc[k * OUT_CH + t], o);
        out[g * OUT_CH + t] = o;
    }
}

// ---------------------------------------------------------------------------
extern "C" void kernel_launch(void* const* d_in, const int* in_sizes, int n_in,
                              void* d_out, int out_size)
{
    // size-based remap (validated in R7: stats of mapped buffers all correct)
    const void *px = nullptr, *pe = nullptr, *pb = nullptr;
    const void *pW1 = nullptr, *pW2 = nullptr, *pb1 = nullptr, *pb2 = nullptr;
    const void *pWc = nullptr, *pbc = nullptr;
    for (int i = 0; i < n_in; i++) {
        int sz = in_sizes[i];
        if      (sz == N_NODES * CH && !px) px = d_in[i];
        else if (sz == 2 * N_EDGES && !pe)  pe = d_in[i];
        else if (sz == N_NODES && !pb)      pb = d_in[i];
        else if (sz == CH * CH)      { if (!pW1) pW1 = d_in[i]; else if (!pW2) pW2 = d_in[i]; }
        else if (sz == CH)           { if (!pb1) pb1 = d_in[i]; else if (!pb2) pb2 = d_in[i]; }
        else if (sz == CH * OUT_CH && !pWc) pWc = d_in[i];
        else if (sz == OUT_CH && !pbc)      pbc = d_in[i];
    }
    const float*        x    = (const float*)px;
    const unsigned int* ebuf = (const unsigned int*)pe;
    const unsigned int* bbuf = (const unsigned int*)pb;
    const float*        W1   = (const float*)pW1;
    const float*        b1   = (const float*)pb1;
    const float*        W2   = (const float*)pW2;
    const float*        b2   = (const float*)pb2;
    const float*        Wc   = (const float*)pWc;
    const float*        bc   = (const float*)pbc;
    float*              out  = (float*)d_out;

    const int NB_N  = (N_NODES + 255) / 256;
    const int NB_E  = (N_EDGES + 255) / 256;
    const int NB_NC = (N_NODES * CH + 255) / 256;
    const int NB_EW = (N_EDGES * 32 + 255) / 256;
    const int NB_GM = (N_NODES + 15) / 16;

    detect_kernel<<<1, 512>>>(ebuf, bbuf);
    conv_edges_kernel<<<(2 * N_EDGES + 255) / 256, 256>>>(ebuf);
    conv_batch_kernel<<<NB_N, 256>>>(bbuf);
    zero_kernel<<<NB_N, 256>>>();
    deg_kernel<<<NB_E, 256>>>();
    dinv_kernel<<<NB_N, 256>>>();

    // ---- layer 1: h = x @ W1 ; agg = A_norm h ----
    gemm_l1_kernel<<<NB_GM, CH>>>(x, W1);
    selfloop_init_kernel<<<NB_NC, 256>>>();
    scatter_kernel<<<NB_EW, 256>>>();

    // ---- layer 2: h = relu(agg + b1) @ W2 ; agg = A_norm h ----
    gemm_l2_kernel<<<NB_GM, CH>>>(W2, b1);
    selfloop_init_kernel<<<NB_NC, 256>>>();
    scatter_kernel<<<NB_EW, 256>>>();

    // ---- relu(agg+b2) -> mean pool -> classify ----
    pool_kernel<<<NB_NC, 256>>>(b2);
    cnt_kernel<<<NB_N, 256>>>();
    cls_kernel<<<NUM_GRAPHS, CH>>>(Wc, bc, out);
}

// round 11
// speedup vs baseline: 1.3364x; 1.3364x over previous
#include <cuda_runtime.h>
#include <cuda_bf16.h>
#include <climits>

#define N_NODES    50000
#define N_EDGES    800000
#define CH         128
#define OUT_CH     10
#define NUM_GRAPHS 128
#define SCAN_THREADS 1024
#define SCAN_CHUNK  ((N_NODES + SCAN_THREADS - 1) / SCAN_THREADS)   // 49

// -------- persistent scratch (device globals; referenced ONLY inside kernels,
//          NEVER passed as host-side launch arguments) --------
__device__ int g_e64_flag;
__device__ int g_b64_flag;
__device__ __align__(16) int   g_eidx[2 * N_EDGES];
__device__ __align__(16) int   g_batch[N_NODES];
__device__ __align__(16) int   g_deg_i[N_NODES];
__device__ __align__(16) int   g_rowptr[N_NODES + 1];
__device__ __align__(16) int   g_cursor[N_NODES];
__device__ __align__(16) float g_dinv[N_NODES];
__device__ __align__(16) int   g_csrc[N_EDGES];      // CSR: src per in-edge
__device__ __align__(16) float g_cnorm[N_EDGES];     // CSR: norm per in-edge
__device__ __align__(16) float g_h[(size_t)N_NODES * CH];
__device__ __align__(16) float g_agg[(size_t)N_NODES * CH];
__device__ __align__(16) int   g_begin[NUM_GRAPHS];
__device__ __align__(16) int   g_end[NUM_GRAPHS];

// ---------------------------------------------------------------------------
// dtype probes (validated on hardware in R7/R10)
__global__ __launch_bounds__(512) void detect_kernel(
    const unsigned int* __restrict__ ebuf, const unsigned int* __restrict__ bbuf)
{
    int t = threadIdx.x;
    int bad_e = (ebuf[2 * t + 1] != 0u);
    int widx = (N_NODES - 1024) + 2 * t + 1;
    int bad_b = (bbuf[widx] != 0u);
    int any_e = __syncthreads_or(bad_e);
    int any_b = __syncthreads_or(bad_b);
    if (t == 0) { g_e64_flag = any_e ? 0 : 1; g_b64_flag = any_b ? 0 : 1; }
}

__global__ void conv_edges_kernel(const unsigned int* __restrict__ ebuf) {
    int i = blockIdx.x * blockDim.x + threadIdx.x;
    if (i >= 2 * N_EDGES) return;
    g_eidx[i] = g_e64_flag ? (int)ebuf[2 * i] : (int)ebuf[i];
}

__global__ void conv_batch_kernel(const unsigned int* __restrict__ bbuf) {
    int i = blockIdx.x * blockDim.x + threadIdx.x;
    if (i >= N_NODES) return;
    int v = g_b64_flag ? (int)bbuf[2 * i] : (int)bbuf[i];
    if ((unsigned)v >= NUM_GRAPHS) v = 0;
    g_batch[i] = v;
}

// ---------------------------------------------------------------------------
__global__ void zero_kernel() {
    int i = blockIdx.x * blockDim.x + threadIdx.x;
    if (i < N_NODES)      g_deg_i[i] = 0;
    if (i < NUM_GRAPHS) { g_begin[i] = INT_MAX; g_end[i] = 0; }
}

__global__ void deg_kernel() {
    int e = blockIdx.x * blockDim.x + threadIdx.x;
    if (e >= N_EDGES) return;
    unsigned d = (unsigned)g_eidx[N_EDGES + e];
    if (d < N_NODES) atomicAdd(&g_deg_i[d], 1);
}

// single-block exclusive scan of deg -> rowptr (+ cursor copy)
__global__ __launch_bounds__(SCAN_THREADS) void scan_kernel() {
    __shared__ int sums[SCAN_THREADS];
    int tid = threadIdx.x;
    int base = tid * SCAN_CHUNK;
    int s = 0;
    for (int i = 0; i < SCAN_CHUNK; i++) {
        int idx = base + i;
        if (idx < N_NODES) s += g_deg_i[idx];
    }
    sums[tid] = s;
    __syncthreads();
    for (int off = 1; off < SCAN_THREADS; off <<= 1) {
        int v = (tid >= off) ? sums[tid - off] : 0;
        __syncthreads();
        sums[tid] += v;
        __syncthreads();
    }
    int run = (tid == 0) ? 0 : sums[tid - 1];
    for (int i = 0; i < SCAN_CHUNK; i++) {
        int idx = base + i;
        if (idx < N_NODES) {
            g_rowptr[idx] = run;
            g_cursor[idx] = run;
            run += g_deg_i[idx];
        }
    }
    if (tid == SCAN_THREADS - 1) g_rowptr[N_NODES] = run;
}

__global__ void dinv_kernel() {
    int i = blockIdx.x * blockDim.x + threadIdx.x;
    if (i < N_NODES) g_dinv[i] = rsqrtf((float)g_deg_i[i] + 1.0f);
}

// scatter edges into CSR slots
__global__ void fill_kernel() {
    int e = blockIdx.x * blockDim.x + threadIdx.x;
    if (e >= N_EDGES) return;
    unsigned s = (unsigned)g_eidx[e];
    unsigned d = (unsigned)g_eidx[N_EDGES + e];
    if (s >= N_NODES || d >= N_NODES) return;
    int pos = atomicAdd(&g_cursor[d], 1);
    g_csrc[pos]  = (int)s;
    g_cnorm[pos] = g_dinv[s] * g_dinv[d];
}

// ---------------------------------------------------------------------------
// layer-1 GEMM: g_h = x @ W1   (validated in R10)
__global__ __launch_bounds__(128) void gemm_l1_kernel(
    const float* __restrict__ X, const float* __restrict__ W)
{
    __shared__ float xs[16][CH];
    const int t = threadIdx.x;
    const int row0 = blockIdx.x * 16;
#pragma unroll
    for (int r = 0; r < 16; r++) {
        int row = row0 + r;
        xs[r][t] = (row < N_NODES) ? X[(size_t)row * CH + t] : 0.f;
    }
    __syncthreads();
    float acc[16];
#pragma unroll
    for (int r = 0; r < 16; r++) acc[r] = 0.f;
#pragma unroll 4
    for (int k = 0; k < CH; k++) {
        float w = W[k * CH + t];
#pragma unroll
        for (int r = 0; r < 16; r++)
            acc[r] = fmaf(xs[r][k], w, acc[r]);
    }
#pragma unroll
    for (int r = 0; r < 16; r++) {
        int row = row0 + r;
        if (row < N_NODES) g_h[(size_t)row * CH + t] = acc[r];
    }
}

// layer-2 GEMM: g_h = relu(g_agg + b1) @ W2   (validated in R10)
__global__ __launch_bounds__(128) void gemm_l2_kernel(
    const float* __restrict__ W, const float* __restrict__ b1)
{
    __shared__ float xs[16][CH];
    const int t = threadIdx.x;
    const int row0 = blockIdx.x * 16;
    float bias = b1[t];
#pragma unroll
    for (int r = 0; r < 16; r++) {
        int row = row0 + r;
        float v = (row < N_NODES) ? g_agg[(size_t)row * CH + t] : 0.f;
        xs[r][t] = fmaxf(v + bias, 0.f);
    }
    __syncthreads();
    float acc[16];
#pragma unroll
    for (int r = 0; r < 16; r++) acc[r] = 0.f;
#pragma unroll 4
    for (int k = 0; k < CH; k++) {
        float w = W[k * CH + t];
#pragma unroll
        for (int r = 0; r < 16; r++)
            acc[r] = fmaf(xs[r][k], w, acc[r]);
    }
#pragma unroll
    for (int r = 0; r < 16; r++) {
        int row = row0 + r;
        if (row < N_NODES) g_h[(size_t)row * CH + t] = acc[r];
    }
}

// ---------------------------------------------------------------------------
// one warp per node, pure gather:
// agg[n] = dinv[n]^2 * h[n] + sum_{e in in(n)} cnorm[e] * h[csrc[e]]
// lane l owns channels [4l, 4l+4).
__global__ __launch_bounds__(256) void aggregate_kernel() {
    int node = (blockIdx.x * blockDim.x + threadIdx.x) >> 5;
    if (node >= N_NODES) return;
    int lane = threadIdx.x & 31;

    float dv = g_dinv[node];
    float w0 = dv * dv;
    float4 acc = *(const float4*)(g_h + (size_t)node * CH + lane * 4);
    acc.x *= w0; acc.y *= w0; acc.z *= w0; acc.w *= w0;

    int e   = g_rowptr[node];
    int end = g_rowptr[node + 1];

    for (; e + 1 < end; e += 2) {          // unroll-by-2, independent loads
        int   s0 = g_csrc[e];
        int   s1 = g_csrc[e + 1];
        float we0 = g_cnorm[e];
        float we1 = g_cnorm[e + 1];
        float4 v0 = *(const float4*)(g_h + (size_t)s0 * CH + lane * 4);
        float4 v1 = *(const float4*)(g_h + (size_t)s1 * CH + lane * 4);
        acc.x = fmaf(we0, v0.x, acc.x); acc.y = fmaf(we0, v0.y, acc.y);
        acc.z = fmaf(we0, v0.z, acc.z); acc.w = fmaf(we0, v0.w, acc.w);
        acc.x = fmaf(we1, v1.x, acc.x); acc.y = fmaf(we1, v1.y, acc.y);
        acc.z = fmaf(we1, v1.z, acc.z); acc.w = fmaf(we1, v1.w, acc.w);
    }
    if (e < end) {
        int   s0 = g_csrc[e];
        float we = g_cnorm[e];
        float4 v = *(const float4*)(g_h + (size_t)s0 * CH + lane * 4);
        acc.x = fmaf(we, v.x, acc.x); acc.y = fmaf(we, v.y, acc.y);
        acc.z = fmaf(we, v.z, acc.z); acc.w = fmaf(we, v.w, acc.w);
    }
    *(float4*)(g_agg + (size_t)node * CH + lane * 4) = acc;
}

// ---------------------------------------------------------------------------
// batch is sorted (verified) -> each graph owns a contiguous node range.
__global__ void bounds_kernel() {
    int i = blockIdx.x * blockDim.x + threadIdx.x;
    if (i >= N_NODES) return;
    int g = g_batch[i];
    atomicMin(&g_begin[g], i);
    atomicMax(&g_end[g], i + 1);
}

// fused: pooled[g] = mean_n relu(agg[n] + b2); out[g] = pooled @ Wc + bc
__global__ __launch_bounds__(CH) void poolcls_kernel(
    const float* __restrict__ b2, const float* __restrict__ Wc,
    const float* __restrict__ bc, float* __restrict__ out)
{
    __shared__ float s[CH];
    int g = blockIdx.x;
    int t = threadIdx.x;
    int b = g_begin[g], e = g_end[g];
    float bias = b2[t];
    float acc = 0.f;
    for (int i = b; i < e; i++)
        acc += fmaxf(g_agg[(size_t)i * CH + t] + bias, 0.f);
    int cnt = (e > b) ? (e - b) : 0;
    s[t] = acc / (float)((cnt > 0) ? cnt : 1);
    __syncthreads();
    if (t < OUT_CH) {
        float o = bc[t];
#pragma unroll 8
        for (int k = 0; k < CH; k++)
            o = fmaf(s[k], Wc[k * OUT_CH + t], o);
        out[g * OUT_CH + t] = o;
    }
}

// ---------------------------------------------------------------------------
extern "C" void kernel_launch(void* const* d_in, const int* in_sizes, int n_in,
                              void* d_out, int out_size)
{
    const void *px = nullptr, *pe = nullptr, *pb = nullptr;
    const void *pW1 = nullptr, *pW2 = nullptr, *pb1 = nullptr, *pb2 = nullptr;
    const void *pWc = nullptr, *pbc = nullptr;
    for (int i = 0; i < n_in; i++) {
        int sz = in_sizes[i];
        if      (sz == N_NODES * CH && !px) px = d_in[i];
        else if (sz == 2 * N_EDGES && !pe)  pe = d_in[i];
        else if (sz == N_NODES && !pb)      pb = d_in[i];
        else if (sz == CH * CH)      { if (!pW1) pW1 = d_in[i]; else if (!pW2) pW2 = d_in[i]; }
        else if (sz == CH)           { if (!pb1) pb1 = d_in[i]; else if (!pb2) pb2 = d_in[i]; }
        else if (sz == CH * OUT_CH && !pWc) pWc = d_in[i];
        else if (sz == OUT_CH && !pbc)      pbc = d_in[i];
    }
    const float*        x    = (const float*)px;
    const unsigned int* ebuf = (const unsigned int*)pe;
    const unsigned int* bbuf = (const unsigned int*)pb;
    const float*        W1   = (const float*)pW1;
    const float*        b1   = (const float*)pb1;
    const float*        W2   = (const float*)pW2;
    const float*        b2   = (const float*)pb2;
    const float*        Wc   = (const float*)pWc;
    const float*        bc   = (const float*)pbc;
    float*              out  = (float*)d_out;

    const int NB_N  = (N_NODES + 255) / 256;
    const int NB_E  = (N_EDGES + 255) / 256;
    const int NB_AG = (N_NODES * 32 + 255) / 256;
    const int NB_GM = (N_NODES + 15) / 16;

    // dtype normalization + CSR build
    detect_kernel<<<1, 512>>>(ebuf, bbuf);
    conv_edges_kernel<<<(2 * N_EDGES + 255) / 256, 256>>>(ebuf);
    conv_batch_kernel<<<NB_N, 256>>>(bbuf);
    zero_kernel<<<NB_N, 256>>>();
    deg_kernel<<<NB_E, 256>>>();
    scan_kernel<<<1, SCAN_THREADS>>>();
    dinv_kernel<<<NB_N, 256>>>();
    fill_kernel<<<NB_E, 256>>>();
    bounds_kernel<<<NB_N, 256>>>();

    // layer 1: h = x @ W1 ; agg = A_norm h
    gemm_l1_kernel<<<NB_GM, CH>>>(x, W1);
    aggregate_kernel<<<NB_AG, 256>>>();

    // layer 2: h = relu(agg + b1) @ W2 ; agg = A_norm h
    gemm_l2_kernel<<<NB_GM, CH>>>(W2, b1);
    aggregate_kernel<<<NB_AG, 256>>>();

    // relu(agg + b2) -> mean pool -> classify (fused)
    poolcls_kernel<<<NUM_GRAPHS, CH>>>(b2, Wc, bc, out);
}